// round 10
// baseline (speedup 1.0000x reference)
#include <cuda_runtime.h>
#include <math.h>

#define Bv   16384
#define Tv   60
#define Hv   128
#define NXv  4
#define NYv  4
#define NYSv 3

#define PADA 133   // A_s row pad (odd*? -> conflict-free transpose stores, 133%32=5)
#define PADW 132   // ws row pad (multiple of 4 for LDS.128 alignment)
#define PADC 130   // c_s row pad (even for float2)

typedef unsigned long long ull;

// ---------------- scratch ----------------
__device__ float g_r1[(size_t)Tv * Bv * Hv];
__device__ float g_r2[(size_t)Tv * Bv * Hv];
__device__ float g_h1[Bv * Hv];
__device__ float g_c1[Bv * Hv];
__device__ float g_W1p[260 * 512];   // permuted+transposed [K=260][512]
__device__ float g_W2p[256 * 512];   // [K=256][512]
__device__ float g_b1p[512];
__device__ float g_b2p[512];
__device__ float g_wcomb[NYv * Hv];
__device__ float g_bcomb[NYv];

// ---------------- f32x2 helpers ----------------
__device__ __forceinline__ ull pk2(float x, float y) {
    ull r; asm("mov.b64 %0, {%1, %2};" : "=l"(r) : "f"(x), "f"(y)); return r;
}
__device__ __forceinline__ void upk2(ull v, float& x, float& y) {
    asm("mov.b64 {%0, %1}, %2;" : "=f"(x), "=f"(y) : "l"(v));
}
__device__ __forceinline__ void ffma2(ull& d, ull a, ull b) {
    asm("fma.rn.f32x2 %0, %1, %2, %0;" : "+l"(d) : "l"(a), "l"(b));
}

__device__ __forceinline__ float sigf(float x) {
    return __fdividef(1.0f, 1.0f + __expf(-x));
}
__device__ __forceinline__ float tanhf_(float x) {
    return __fdividef(2.0f, 1.0f + __expf(-2.0f * x)) - 1.0f;
}

// ---------------- init: h0/c0 for layer1 ----------------
__global__ void init_kernel(const float* __restrict__ sfc,
                            const float* __restrict__ Ws1, const float* __restrict__ bs1,
                            const float* __restrict__ Ws2, const float* __restrict__ bs2)
{
    int i = blockIdx.x * blockDim.x + threadIdx.x;
    if (i >= Bv * Hv) return;
    int b = i >> 7, j = i & 127;
    float s0 = sfc[b * 3 + 0], s1 = sfc[b * 3 + 1], s2 = sfc[b * 3 + 2];
    float a1 = bs1[j] + s0 * Ws1[j * 3 + 0] + s1 * Ws1[j * 3 + 1] + s2 * Ws1[j * 3 + 2];
    float a2 = bs2[j] + s0 * Ws2[j * 3 + 0] + s1 * Ws2[j * 3 + 1] + s2 * Ws2[j * 3 + 2];
    g_h1[i] = tanhf(a1);
    g_c1[i] = tanhf(a2);
}

// ---------------- prep: permuted weights/biases + folded output projection ----------------
// Column permutation within each 128-wide chunk ci: n = jj*4 + q  (jj: hidden-in-chunk, q: gate)
__global__ void prep_kernel(const float* __restrict__ Wih1, const float* __restrict__ Whh1,
                            const float* __restrict__ bih1, const float* __restrict__ bhh1,
                            const float* __restrict__ Wih2, const float* __restrict__ Whh2,
                            const float* __restrict__ bih2, const float* __restrict__ bhh2,
                            const float* __restrict__ Wlat, const float* __restrict__ blat,
                            const float* __restrict__ Wout, const float* __restrict__ bout)
{
    int idx = blockIdx.x * blockDim.x + threadIdx.x;
    const int N1 = 260 * 512, N2 = 256 * 512;
    if (idx < N1) {
        int k = idx >> 9, m = idx & 511;
        int ci = m >> 7, n = m & 127, q = n & 3, jj = n >> 2;
        int g = q * 128 + ci * 32 + jj;
        g_W1p[idx] = (k < 132) ? Wih1[g * 132 + k] : Whh1[g * 128 + (k - 132)];
        return;
    }
    int i2 = idx - N1;
    if (i2 < N2) {
        int k = i2 >> 9, m = i2 & 511;
        int ci = m >> 7, n = m & 127, q = n & 3, jj = n >> 2;
        int g = q * 128 + ci * 32 + jj;
        g_W2p[i2] = (k < 128) ? Wih2[g * 128 + k] : Whh2[g * 128 + (k - 128)];
        return;
    }
    int i3 = idx - N1 - N2;
    if (i3 < 512) {
        int ci = i3 >> 7, n = i3 & 127, q = n & 3, jj = n >> 2;
        int g = q * 128 + ci * 32 + jj;
        g_b1p[i3] = bih1[g] + bhh1[g];
        g_b2p[i3] = bih2[g] + bhh2[g];
        // folded output projection: Wcomb = Wout @ Wlat
        int y = i3 >> 7, j = i3 & 127;
        float acc = 0.0f;
        for (int k = 0; k < Hv; k++) acc += Wout[y * Hv + k] * Wlat[k * Hv + j];
        g_wcomb[i3] = acc;
        if (i3 < NYv) {
            float bb = bout[i3];
            for (int k = 0; k < Hv; k++) bb += Wout[i3 * Hv + k] * blat[k];
            g_bcomb[i3] = bb;
        }
    }
}

// ---------------- persistent fused 2-layer LSTM ----------------
// Grid: 128 CTAs x 256 threads. CTA owns batch rows [cta*128, cta*128+128).
// Runs layer1 (reverse time) then layer2 (forward), 60 steps each, locally.
// Inner GEMM: M=128 x N=128-chunk x K, f32x2 packed FMA, 8 rows x 4 col-pairs per thread.
__global__ __launch_bounds__(256, 1) void rnn_persist(
    const float* __restrict__ inputs_main,   // [B][T][4]
    const float* __restrict__ mem0,          // [B][T][128]
    const float* __restrict__ h1_0, const float* __restrict__ c1_0,
    const float* __restrict__ hx2,  const float* __restrict__ cx2,
    const float* __restrict__ W1p,  const float* __restrict__ b1p,
    const float* __restrict__ W2p,  const float* __restrict__ b2p,
    float* __restrict__ r1, float* __restrict__ r2)
{
    extern __shared__ float sm[];
    float* A_s    = sm;                           // [260][PADA] K-major activations
    float* c_s    = sm + 260 * PADA;              // [128][PADC]
    float* ws     = c_s + 128 * PADC;             // [32][PADW]  weight panel
    float* bias_s = ws + 32 * PADW;               // [512]

    const int tid = threadIdx.x;
    const int tx = tid & 15;
    const int ty = tid >> 4;
    const int b0 = blockIdx.x * 128;
    const size_t SLAB = (size_t)Bv * Hv;

    for (int layer = 0; layer < 2; ++layer) {
        const int KA   = layer ? 128 : 132;   // non-recurrent K
        const int KTOT = KA + 128;
        const int NPAN = (KTOT + 31) >> 5;
        const float* Wp = layer ? W2p : W1p;
        const float* bp = layer ? b2p : b1p;

        // load bias + initial c for this layer
        __syncthreads();
        for (int i = tid; i < 512; i += 256) bias_s[i] = bp[i];
        {
            const float* c0 = layer ? cx2 : c1_0;
            for (int i = tid; i < 128 * 128; i += 256) {
                int r = i >> 7, k = i & 127;
                c_s[r * PADC + k] = c0[(size_t)(b0 + r) * 128 + k];
            }
        }

        for (int t = 0; t < Tv; ++t) {
            const int ta = layer ? t : (Tv - 1 - t);   // actual time index
            const float* hsrc = (t == 0)
                ? (layer ? hx2 : h1_0)
                : (layer ? r2 + (size_t)(t - 1) * SLAB : r1 + (size_t)(ta + 1) * SLAB);
            float* hdst = layer ? r2 + (size_t)t * SLAB : r1 + (size_t)ta * SLAB;

            __syncthreads();   // protect A_s / ws from previous step's readers

            // ---- stage activations K-major into A_s ----
            if (layer == 0) {
                for (int i = tid; i < 512; i += 256) {           // x: k 0..3
                    int r = i >> 2, f = i & 3;
                    A_s[f * PADA + r] = inputs_main[(size_t)(b0 + r) * (Tv * NXv) + ta * NXv + f];
                }
                for (int i = tid; i < 128 * 128; i += 256) {     // mem0: k 4..131
                    int r = i >> 7, k = i & 127;
                    A_s[(4 + k) * PADA + r] = mem0[(size_t)(b0 + r) * (Tv * Hv) + t * Hv + k];
                }
            } else {
                for (int i = tid; i < 128 * 128; i += 256) {     // r1_t: k 0..127
                    int r = i >> 7, k = i & 127;
                    A_s[k * PADA + r] = r1[(size_t)t * SLAB + (size_t)(b0 + r) * 128 + k];
                }
            }
            for (int i = tid; i < 128 * 128; i += 256) {         // h: k KA..KA+127
                int r = i >> 7, k = i & 127;
                A_s[(KA + k) * PADA + r] = hsrc[(size_t)(b0 + r) * 128 + k];
            }

            // ---- 4 N-chunks of 128 permuted gate-columns ----
            for (int ci = 0; ci < 4; ++ci) {
                ull acc[8][4];
#pragma unroll
                for (int p = 0; p < 4; ++p) {
                    float2 bb = *(const float2*)&bias_s[ci * 128 + 8 * tx + 2 * p];
                    ull bv = pk2(bb.x, bb.y);
#pragma unroll
                    for (int i = 0; i < 8; i++) acc[i][p] = bv;
                }

                for (int p = 0; p < NPAN; ++p) {
                    const int kbase = p * 32;
                    const int pkk = (kbase + 32 <= KTOT) ? 32 : (KTOT - kbase);
                    __syncthreads();
                    const float* wsrc = Wp + (size_t)kbase * 512 + ci * 128;
                    for (int i = tid; i < (pkk << 7); i += 256) {
                        int kk = i >> 7, n = i & 127;
                        ws[kk * PADW + n] = wsrc[(size_t)kk * 512 + n];
                    }
                    __syncthreads();

                    const float* ap = A_s + kbase * PADA + ty * 8;
                    const float* wq = ws + 8 * tx;

#define GEMM_BODY(kk)                                                           \
    {                                                                           \
        float a_[8];                                                            \
        _Pragma("unroll")                                                       \
        for (int i = 0; i < 8; i++) a_[i] = ap[(kk) * PADA + i];                \
        float4 w0 = *(const float4*)(wq + (kk) * PADW);                         \
        float4 w1 = *(const float4*)(wq + (kk) * PADW + 4);                     \
        ull wq0 = pk2(w0.x, w0.y), wq1 = pk2(w0.z, w0.w);                       \
        ull wq2 = pk2(w1.x, w1.y), wq3 = pk2(w1.z, w1.w);                       \
        _Pragma("unroll")                                                       \
        for (int i = 0; i < 8; i++) {                                           \
            ull ad = pk2(a_[i], a_[i]);                                         \
            ffma2(acc[i][0], ad, wq0);                                          \
            ffma2(acc[i][1], ad, wq1);                                          \
            ffma2(acc[i][2], ad, wq2);                                          \
            ffma2(acc[i][3], ad, wq3);                                          \
        }                                                                       \
    }

                    if (pkk == 32) {
#pragma unroll 4
                        for (int kk = 0; kk < 32; ++kk) GEMM_BODY(kk)
                    } else {
                        for (int kk = 0; kk < pkk; ++kk) GEMM_BODY(kk)
                    }
#undef GEMM_BODY
                }

                // ---- cell epilogue: thread owns rows ty*8..+7, hiddens ci*32+2tx, +1 ----
                const int jg = ci * 32 + 2 * tx;
#pragma unroll
                for (int i = 0; i < 8; i++) {
                    const int row = ty * 8 + i;
                    float zi0, zf0, zg0, zo0, zi1, zf1, zg1, zo1;
                    upk2(acc[i][0], zi0, zf0);
                    upk2(acc[i][1], zg0, zo0);
                    upk2(acc[i][2], zi1, zf1);
                    upk2(acc[i][3], zg1, zo1);
                    float2 cc = *(float2*)&c_s[row * PADC + jg];
                    float c0n = sigf(zf0) * cc.x + sigf(zi0) * tanhf_(zg0);
                    float c1n = sigf(zf1) * cc.y + sigf(zi1) * tanhf_(zg1);
                    float h0 = sigf(zo0) * tanhf_(c0n);
                    float h1 = sigf(zo1) * tanhf_(c1n);
                    *(float2*)&c_s[row * PADC + jg] = make_float2(c0n, c1n);
                    *(float2*)&hdst[(size_t)(b0 + row) * 128 + jg] = make_float2(h0, h1);
                }
            }
        }
    }
}

// ---------------- final projection: out = r2 @ Wcomb^T + bcomb ----------------
__global__ void out_kernel(const float* __restrict__ r2, float* __restrict__ out)
{
    __shared__ float sw[NYv * 129];
    __shared__ float sr[32][129];
    int tid = threadIdx.x;
    for (int i = tid; i < NYv * Hv; i += 128) {
        int y = i >> 7, k = i & 127;
        sw[y * 129 + k] = g_wcomb[i];
    }
    size_t base = (size_t)blockIdx.x * 32 * Hv;
    for (int i = tid; i < 32 * Hv; i += 128) {
        int rr = i >> 7, kk = i & 127;
        sr[rr][kk] = r2[base + i];
    }
    __syncthreads();
    int r = tid >> 2, y = tid & 3;
    int n = blockIdx.x * 32 + r;
    int t = n >> 14;
    int b = n & (Bv - 1);
    float acc = g_bcomb[y];
#pragma unroll 4
    for (int k = 0; k < Hv; k++) acc += sw[y * 129 + k] * sr[r][k];
    out[((size_t)b * Tv + t) * NYv + y] = acc;
}

// ---------------- out_sfc = hN @ Wsfc^T + bsfc ----------------
__global__ void sfc_kernel(const float* __restrict__ Wsfc, const float* __restrict__ bsfc,
                           const float* __restrict__ hN, float* __restrict__ osfc)
{
    int i = blockIdx.x * blockDim.x + threadIdx.x;
    if (i >= Bv * NYSv) return;
    int b = i / 3, y = i - b * 3;
    const float* h = hN + (size_t)b * Hv;
    float acc = bsfc[y];
#pragma unroll 4
    for (int k = 0; k < Hv; k++) acc += Wsfc[y * Hv + k] * h[k];
    osfc[i] = acc;
}

// ---------------- launch ----------------
extern "C" void kernel_launch(void* const* d_in, const int* in_sizes, int n_in,
                              void* d_out, int out_size)
{
    const float* inputs_main = (const float*)d_in[0];
    const float* inputs_sfc  = (const float*)d_in[1];
    const float* mem0        = (const float*)d_in[2];
    const float* hx2         = (const float*)d_in[3];
    const float* cx2         = (const float*)d_in[4];
    const float* Ws1  = (const float*)d_in[5];
    const float* bs1  = (const float*)d_in[6];
    const float* Ws2  = (const float*)d_in[7];
    const float* bs2  = (const float*)d_in[8];
    const float* Wih1 = (const float*)d_in[9];
    const float* Whh1 = (const float*)d_in[10];
    const float* bih1 = (const float*)d_in[11];
    const float* bhh1 = (const float*)d_in[12];
    const float* Wih2 = (const float*)d_in[13];
    const float* Whh2 = (const float*)d_in[14];
    const float* bih2 = (const float*)d_in[15];
    const float* bhh2 = (const float*)d_in[16];
    const float* Wlat = (const float*)d_in[17];
    const float* blat = (const float*)d_in[18];
    const float* Wout = (const float*)d_in[19];
    const float* bout = (const float*)d_in[20];
    const float* Wsfc = (const float*)d_in[21];
    const float* bsfc = (const float*)d_in[22];
    float* out = (float*)d_out;

    float *r1, *r2, *h1, *c1, *W1p, *W2p, *b1p, *b2p;
    cudaGetSymbolAddress((void**)&r1, g_r1);
    cudaGetSymbolAddress((void**)&r2, g_r2);
    cudaGetSymbolAddress((void**)&h1, g_h1);
    cudaGetSymbolAddress((void**)&c1, g_c1);
    cudaGetSymbolAddress((void**)&W1p, g_W1p);
    cudaGetSymbolAddress((void**)&W2p, g_W2p);
    cudaGetSymbolAddress((void**)&b1p, g_b1p);
    cudaGetSymbolAddress((void**)&b2p, g_b2p);

    const int SMEM_BYTES = (260 * PADA + 128 * PADC + 32 * PADW + 512) * 4;
    cudaFuncSetAttribute(rnn_persist, cudaFuncAttributeMaxDynamicSharedMemorySize, SMEM_BYTES);

    init_kernel<<<(Bv * Hv + 255) / 256, 256>>>(inputs_sfc, Ws1, bs1, Ws2, bs2);

    const int PREP_N = 260 * 512 + 256 * 512 + 512;
    prep_kernel<<<(PREP_N + 255) / 256, 256>>>(Wih1, Whh1, bih1, bhh1,
                                               Wih2, Whh2, bih2, bhh2,
                                               Wlat, blat, Wout, bout);

    rnn_persist<<<128, 256, SMEM_BYTES>>>(inputs_main, mem0, h1, c1, hx2, cx2,
                                          W1p, b1p, W2p, b2p, r1, r2);

    out_kernel<<<(Bv * Tv) / 32, 128>>>(r2, out);
    sfc_kernel<<<(Bv * NYSv + 255) / 256, 256>>>(Wsfc, bsfc,
                                                 r2 + (size_t)(Tv - 1) * Bv * Hv,
                                                 out + (size_t)Bv * Tv * NYv);
}

// round 11
// speedup vs baseline: 1.0016x; 1.0016x over previous
#include <cuda_runtime.h>
#include <math.h>

#define Bv   16384
#define Tv   60
#define Hv   128
#define NXv  4
#define NYv  4
#define NYSv 3

#define PADA 133   // A_s row pad (odd*? -> conflict-free transpose stores, 133%32=5)
#define PADW 132   // ws row pad (multiple of 4 for LDS.128 alignment)
#define PADC 130   // c_s row pad (even for float2)

typedef unsigned long long ull;

// ---------------- scratch ----------------
__device__ float g_r1[(size_t)Tv * Bv * Hv];
__device__ float g_r2[(size_t)Tv * Bv * Hv];
__device__ float g_h1[Bv * Hv];
__device__ float g_c1[Bv * Hv];
__device__ float g_W1p[260 * 512];   // permuted+transposed [K=260][512]
__device__ float g_W2p[256 * 512];   // [K=256][512]
__device__ float g_b1p[512];
__device__ float g_b2p[512];
__device__ float g_wcomb[NYv * Hv];
__device__ float g_bcomb[NYv];

// ---------------- f32x2 helpers ----------------
__device__ __forceinline__ ull pk2(float x, float y) {
    ull r; asm("mov.b64 %0, {%1, %2};" : "=l"(r) : "f"(x), "f"(y)); return r;
}
__device__ __forceinline__ void upk2(ull v, float& x, float& y) {
    asm("mov.b64 {%0, %1}, %2;" : "=f"(x), "=f"(y) : "l"(v));
}
__device__ __forceinline__ void ffma2(ull& d, ull a, ull b) {
    asm("fma.rn.f32x2 %0, %1, %2, %0;" : "+l"(d) : "l"(a), "l"(b));
}

__device__ __forceinline__ float sigf(float x) {
    return __fdividef(1.0f, 1.0f + __expf(-x));
}
__device__ __forceinline__ float tanhf_(float x) {
    return __fdividef(2.0f, 1.0f + __expf(-2.0f * x)) - 1.0f;
}

// ---------------- init: h0/c0 for layer1 ----------------
__global__ void init_kernel(const float* __restrict__ sfc,
                            const float* __restrict__ Ws1, const float* __restrict__ bs1,
                            const float* __restrict__ Ws2, const float* __restrict__ bs2)
{
    int i = blockIdx.x * blockDim.x + threadIdx.x;
    if (i >= Bv * Hv) return;
    int b = i >> 7, j = i & 127;
    float s0 = sfc[b * 3 + 0], s1 = sfc[b * 3 + 1], s2 = sfc[b * 3 + 2];
    float a1 = bs1[j] + s0 * Ws1[j * 3 + 0] + s1 * Ws1[j * 3 + 1] + s2 * Ws1[j * 3 + 2];
    float a2 = bs2[j] + s0 * Ws2[j * 3 + 0] + s1 * Ws2[j * 3 + 1] + s2 * Ws2[j * 3 + 2];
    g_h1[i] = tanhf(a1);
    g_c1[i] = tanhf(a2);
}

// ---------------- prep: permuted weights/biases + folded output projection ----------------
// Column permutation within each 128-wide chunk ci: n = jj*4 + q  (jj: hidden-in-chunk, q: gate)
__global__ void prep_kernel(const float* __restrict__ Wih1, const float* __restrict__ Whh1,
                            const float* __restrict__ bih1, const float* __restrict__ bhh1,
                            const float* __restrict__ Wih2, const float* __restrict__ Whh2,
                            const float* __restrict__ bih2, const float* __restrict__ bhh2,
                            const float* __restrict__ Wlat, const float* __restrict__ blat,
                            const float* __restrict__ Wout, const float* __restrict__ bout)
{
    int idx = blockIdx.x * blockDim.x + threadIdx.x;
    const int N1 = 260 * 512, N2 = 256 * 512;
    if (idx < N1) {
        int k = idx >> 9, m = idx & 511;
        int ci = m >> 7, n = m & 127, q = n & 3, jj = n >> 2;
        int g = q * 128 + ci * 32 + jj;
        g_W1p[idx] = (k < 132) ? Wih1[g * 132 + k] : Whh1[g * 128 + (k - 132)];
        return;
    }
    int i2 = idx - N1;
    if (i2 < N2) {
        int k = i2 >> 9, m = i2 & 511;
        int ci = m >> 7, n = m & 127, q = n & 3, jj = n >> 2;
        int g = q * 128 + ci * 32 + jj;
        g_W2p[i2] = (k < 128) ? Wih2[g * 128 + k] : Whh2[g * 128 + (k - 128)];
        return;
    }
    int i3 = idx - N1 - N2;
    if (i3 < 512) {
        int ci = i3 >> 7, n = i3 & 127, q = n & 3, jj = n >> 2;
        int g = q * 128 + ci * 32 + jj;
        g_b1p[i3] = bih1[g] + bhh1[g];
        g_b2p[i3] = bih2[g] + bhh2[g];
        // folded output projection: Wcomb = Wout @ Wlat
        int y = i3 >> 7, j = i3 & 127;
        float acc = 0.0f;
        for (int k = 0; k < Hv; k++) acc += Wout[y * Hv + k] * Wlat[k * Hv + j];
        g_wcomb[i3] = acc;
        if (i3 < NYv) {
            float bb = bout[i3];
            for (int k = 0; k < Hv; k++) bb += Wout[i3 * Hv + k] * blat[k];
            g_bcomb[i3] = bb;
        }
    }
}

// ---------------- persistent fused 2-layer LSTM ----------------
// Grid: 128 CTAs x 256 threads. CTA owns batch rows [cta*128, cta*128+128).
// Runs layer1 (reverse time) then layer2 (forward), 60 steps each, locally.
// Inner GEMM: M=128 x N=128-chunk x K, f32x2 packed FMA, 8 rows x 4 col-pairs per thread.
__global__ __launch_bounds__(256, 1) void rnn_persist(
    const float* __restrict__ inputs_main,   // [B][T][4]
    const float* __restrict__ mem0,          // [B][T][128]
    const float* __restrict__ h1_0, const float* __restrict__ c1_0,
    const float* __restrict__ hx2,  const float* __restrict__ cx2,
    const float* __restrict__ W1p,  const float* __restrict__ b1p,
    const float* __restrict__ W2p,  const float* __restrict__ b2p,
    float* __restrict__ r1, float* __restrict__ r2)
{
    extern __shared__ float sm[];
    float* A_s    = sm;                           // [260][PADA] K-major activations
    float* c_s    = sm + 260 * PADA;              // [128][PADC]
    float* ws     = c_s + 128 * PADC;             // [32][PADW]  weight panel
    float* bias_s = ws + 32 * PADW;               // [512]

    const int tid = threadIdx.x;
    const int tx = tid & 15;
    const int ty = tid >> 4;
    const int b0 = blockIdx.x * 128;
    const size_t SLAB = (size_t)Bv * Hv;

    for (int layer = 0; layer < 2; ++layer) {
        const int KA   = layer ? 128 : 132;   // non-recurrent K
        const int KTOT = KA + 128;
        const int NPAN = (KTOT + 31) >> 5;
        const float* Wp = layer ? W2p : W1p;
        const float* bp = layer ? b2p : b1p;

        // load bias + initial c for this layer
        __syncthreads();
        for (int i = tid; i < 512; i += 256) bias_s[i] = bp[i];
        {
            const float* c0 = layer ? cx2 : c1_0;
            for (int i = tid; i < 128 * 128; i += 256) {
                int r = i >> 7, k = i & 127;
                c_s[r * PADC + k] = c0[(size_t)(b0 + r) * 128 + k];
            }
        }

        for (int t = 0; t < Tv; ++t) {
            const int ta = layer ? t : (Tv - 1 - t);   // actual time index
            const float* hsrc = (t == 0)
                ? (layer ? hx2 : h1_0)
                : (layer ? r2 + (size_t)(t - 1) * SLAB : r1 + (size_t)(ta + 1) * SLAB);
            float* hdst = layer ? r2 + (size_t)t * SLAB : r1 + (size_t)ta * SLAB;

            __syncthreads();   // protect A_s / ws from previous step's readers

            // ---- stage activations K-major into A_s ----
            if (layer == 0) {
                for (int i = tid; i < 512; i += 256) {           // x: k 0..3
                    int r = i >> 2, f = i & 3;
                    A_s[f * PADA + r] = inputs_main[(size_t)(b0 + r) * (Tv * NXv) + ta * NXv + f];
                }
                for (int i = tid; i < 128 * 128; i += 256) {     // mem0: k 4..131
                    int r = i >> 7, k = i & 127;
                    A_s[(4 + k) * PADA + r] = mem0[(size_t)(b0 + r) * (Tv * Hv) + t * Hv + k];
                }
            } else {
                for (int i = tid; i < 128 * 128; i += 256) {     // r1_t: k 0..127
                    int r = i >> 7, k = i & 127;
                    A_s[k * PADA + r] = r1[(size_t)t * SLAB + (size_t)(b0 + r) * 128 + k];
                }
            }
            for (int i = tid; i < 128 * 128; i += 256) {         // h: k KA..KA+127
                int r = i >> 7, k = i & 127;
                A_s[(KA + k) * PADA + r] = hsrc[(size_t)(b0 + r) * 128 + k];
            }

            // ---- 4 N-chunks of 128 permuted gate-columns ----
            for (int ci = 0; ci < 4; ++ci) {
                ull acc[8][4];
#pragma unroll
                for (int p = 0; p < 4; ++p) {
                    float2 bb = *(const float2*)&bias_s[ci * 128 + 8 * tx + 2 * p];
                    ull bv = pk2(bb.x, bb.y);
#pragma unroll
                    for (int i = 0; i < 8; i++) acc[i][p] = bv;
                }

                for (int p = 0; p < NPAN; ++p) {
                    const int kbase = p * 32;
                    const int pkk = (kbase + 32 <= KTOT) ? 32 : (KTOT - kbase);
                    __syncthreads();
                    const float* wsrc = Wp + (size_t)kbase * 512 + ci * 128;
                    for (int i = tid; i < (pkk << 7); i += 256) {
                        int kk = i >> 7, n = i & 127;
                        ws[kk * PADW + n] = wsrc[(size_t)kk * 512 + n];
                    }
                    __syncthreads();

                    const float* ap = A_s + kbase * PADA + ty * 8;
                    const float* wq = ws + 8 * tx;

#define GEMM_BODY(kk)                                                           \
    {                                                                           \
        float a_[8];                                                            \
        _Pragma("unroll")                                                       \
        for (int i = 0; i < 8; i++) a_[i] = ap[(kk) * PADA + i];                \
        float4 w0 = *(const float4*)(wq + (kk) * PADW);                         \
        float4 w1 = *(const float4*)(wq + (kk) * PADW + 4);                     \
        ull wq0 = pk2(w0.x, w0.y), wq1 = pk2(w0.z, w0.w);                       \
        ull wq2 = pk2(w1.x, w1.y), wq3 = pk2(w1.z, w1.w);                       \
        _Pragma("unroll")                                                       \
        for (int i = 0; i < 8; i++) {                                           \
            ull ad = pk2(a_[i], a_[i]);                                         \
            ffma2(acc[i][0], ad, wq0);                                          \
            ffma2(acc[i][1], ad, wq1);                                          \
            ffma2(acc[i][2], ad, wq2);                                          \
            ffma2(acc[i][3], ad, wq3);                                          \
        }                                                                       \
    }

                    if (pkk == 32) {
#pragma unroll 4
                        for (int kk = 0; kk < 32; ++kk) GEMM_BODY(kk)
                    } else {
                        for (int kk = 0; kk < pkk; ++kk) GEMM_BODY(kk)
                    }
#undef GEMM_BODY
                }

                // ---- cell epilogue: thread owns rows ty*8..+7, hiddens ci*32+2tx, +1 ----
                const int jg = ci * 32 + 2 * tx;
#pragma unroll
                for (int i = 0; i < 8; i++) {
                    const int row = ty * 8 + i;
                    float zi0, zf0, zg0, zo0, zi1, zf1, zg1, zo1;
                    upk2(acc[i][0], zi0, zf0);
                    upk2(acc[i][1], zg0, zo0);
                    upk2(acc[i][2], zi1, zf1);
                    upk2(acc[i][3], zg1, zo1);
                    float2 cc = *(float2*)&c_s[row * PADC + jg];
                    float c0n = sigf(zf0) * cc.x + sigf(zi0) * tanhf_(zg0);
                    float c1n = sigf(zf1) * cc.y + sigf(zi1) * tanhf_(zg1);
                    float h0 = sigf(zo0) * tanhf_(c0n);
                    float h1 = sigf(zo1) * tanhf_(c1n);
                    *(float2*)&c_s[row * PADC + jg] = make_float2(c0n, c1n);
                    *(float2*)&hdst[(size_t)(b0 + row) * 128 + jg] = make_float2(h0, h1);
                }
            }
        }
    }
}

// ---------------- final projection: out = r2 @ Wcomb^T + bcomb ----------------
__global__ void out_kernel(const float* __restrict__ r2, float* __restrict__ out)
{
    __shared__ float sw[NYv * 129];
    __shared__ float sr[32][129];
    int tid = threadIdx.x;
    for (int i = tid; i < NYv * Hv; i += 128) {
        int y = i >> 7, k = i & 127;
        sw[y * 129 + k] = g_wcomb[i];
    }
    size_t base = (size_t)blockIdx.x * 32 * Hv;
    for (int i = tid; i < 32 * Hv; i += 128) {
        int rr = i >> 7, kk = i & 127;
        sr[rr][kk] = r2[base + i];
    }
    __syncthreads();
    int r = tid >> 2, y = tid & 3;
    int n = blockIdx.x * 32 + r;
    int t = n >> 14;
    int b = n & (Bv - 1);
    float acc = g_bcomb[y];
#pragma unroll 4
    for (int k = 0; k < Hv; k++) acc += sw[y * 129 + k] * sr[r][k];
    out[((size_t)b * Tv + t) * NYv + y] = acc;
}

// ---------------- out_sfc = hN @ Wsfc^T + bsfc ----------------
__global__ void sfc_kernel(const float* __restrict__ Wsfc, const float* __restrict__ bsfc,
                           const float* __restrict__ hN, float* __restrict__ osfc)
{
    int i = blockIdx.x * blockDim.x + threadIdx.x;
    if (i >= Bv * NYSv) return;
    int b = i / 3, y = i - b * 3;
    const float* h = hN + (size_t)b * Hv;
    float acc = bsfc[y];
#pragma unroll 4
    for (int k = 0; k < Hv; k++) acc += Wsfc[y * Hv + k] * h[k];
    osfc[i] = acc;
}

// ---------------- launch ----------------
extern "C" void kernel_launch(void* const* d_in, const int* in_sizes, int n_in,
                              void* d_out, int out_size)
{
    const float* inputs_main = (const float*)d_in[0];
    const float* inputs_sfc  = (const float*)d_in[1];
    const float* mem0        = (const float*)d_in[2];
    const float* hx2         = (const float*)d_in[3];
    const float* cx2         = (const float*)d_in[4];
    const float* Ws1  = (const float*)d_in[5];
    const float* bs1  = (const float*)d_in[6];
    const float* Ws2  = (const float*)d_in[7];
    const float* bs2  = (const float*)d_in[8];
    const float* Wih1 = (const float*)d_in[9];
    const float* Whh1 = (const float*)d_in[10];
    const float* bih1 = (const float*)d_in[11];
    const float* bhh1 = (const float*)d_in[12];
    const float* Wih2 = (const float*)d_in[13];
    const float* Whh2 = (const float*)d_in[14];
    const float* bih2 = (const float*)d_in[15];
    const float* bhh2 = (const float*)d_in[16];
    const float* Wlat = (const float*)d_in[17];
    const float* blat = (const float*)d_in[18];
    const float* Wout = (const float*)d_in[19];
    const float* bout = (const float*)d_in[20];
    const float* Wsfc = (const float*)d_in[21];
    const float* bsfc = (const float*)d_in[22];
    float* out = (float*)d_out;

    float *r1, *r2, *h1, *c1, *W1p, *W2p, *b1p, *b2p;
    cudaGetSymbolAddress((void**)&r1, g_r1);
    cudaGetSymbolAddress((void**)&r2, g_r2);
    cudaGetSymbolAddress((void**)&h1, g_h1);
    cudaGetSymbolAddress((void**)&c1, g_c1);
    cudaGetSymbolAddress((void**)&W1p, g_W1p);
    cudaGetSymbolAddress((void**)&W2p, g_W2p);
    cudaGetSymbolAddress((void**)&b1p, g_b1p);
    cudaGetSymbolAddress((void**)&b2p, g_b2p);

    const int SMEM_BYTES = (260 * PADA + 128 * PADC + 32 * PADW + 512) * 4;
    cudaFuncSetAttribute(rnn_persist, cudaFuncAttributeMaxDynamicSharedMemorySize, SMEM_BYTES);

    init_kernel<<<(Bv * Hv + 255) / 256, 256>>>(inputs_sfc, Ws1, bs1, Ws2, bs2);

    const int PREP_N = 260 * 512 + 256 * 512 + 512;
    prep_kernel<<<(PREP_N + 255) / 256, 256>>>(Wih1, Whh1, bih1, bhh1,
                                               Wih2, Whh2, bih2, bhh2,
                                               Wlat, blat, Wout, bout);

    rnn_persist<<<128, 256, SMEM_BYTES>>>(inputs_main, mem0, h1, c1, hx2, cx2,
                                          W1p, b1p, W2p, b2p, r1, r2);

    out_kernel<<<(Bv * Tv) / 32, 128>>>(r2, out);
    sfc_kernel<<<(Bv * NYSv + 255) / 256, 256>>>(Wsfc, bsfc,
                                                 r2 + (size_t)(Tv - 1) * Bv * Hv,
                                                 out + (size_t)Bv * Tv * NYv);
}